// round 15
// baseline (speedup 1.0000x reference)
#include <cuda_runtime.h>
#include <math.h>

#define LL 512
#define BB 2
#define DD 512
#define HH 8
#define DTT 64
#define NUMK 100

// libdevice accurate expf (O1 class — matches reference softmax arithmetic class)
extern "C" __device__ float __nv_expf(float);

// ---- scratch (device globals, allowed) ----
__device__ float g_qb[BB*LL*DD];           // [b][l][d]
__device__ float g_kb[BB*LL*DD];
__device__ float g_vb[BB*LL*DD];
__device__ float g_s[BB*HH*LL*LL];         // raw scores /8: [b][h][l][m]
__device__ float g_attn[BB*HH*LL*LL];      // softmax
__device__ int   g_idx[BB*HH*LL*NUMK];     // top-100 ascending indices
__device__ float g_T[BB*LL*8*8*DD];        // [b][lv][cv][j][o]  (128 MB)

// 16 FMA micro-tile over a 64-deep K chunk, smem pitch 68 floats.
// Sequential ascending-k FMA chain (matches Eigen gebp / reference chains).
#define TILE_COMPUTE()                                                        \
  _Pragma("unroll")                                                           \
  for (int kc = 0; kc < 64; kc++) {                                           \
    float4 a  = *(const float4*)(As + kc*68 + mi);                            \
    float4 b4 = *(const float4*)(Bs + kc*68 + ni);                            \
    acc[0][0] = fmaf(a.x,b4.x,acc[0][0]); acc[0][1] = fmaf(a.x,b4.y,acc[0][1]);\
    acc[0][2] = fmaf(a.x,b4.z,acc[0][2]); acc[0][3] = fmaf(a.x,b4.w,acc[0][3]);\
    acc[1][0] = fmaf(a.y,b4.x,acc[1][0]); acc[1][1] = fmaf(a.y,b4.y,acc[1][1]);\
    acc[1][2] = fmaf(a.y,b4.z,acc[1][2]); acc[1][3] = fmaf(a.y,b4.w,acc[1][3]);\
    acc[2][0] = fmaf(a.z,b4.x,acc[2][0]); acc[2][1] = fmaf(a.z,b4.y,acc[2][1]);\
    acc[2][2] = fmaf(a.z,b4.z,acc[2][2]); acc[2][3] = fmaf(a.z,b4.w,acc[2][3]);\
    acc[3][0] = fmaf(a.w,b4.x,acc[3][0]); acc[3][1] = fmaf(a.w,b4.y,acc[3][1]);\
    acc[3][2] = fmaf(a.w,b4.z,acc[3][2]); acc[3][3] = fmaf(a.w,b4.w,acc[3][3]);\
  }

#define TILE_LOAD(arow, brow)                                                 \
  _Pragma("unroll")                                                           \
  for (int qd = 0; qd < 4; qd++) {                                            \
    int f4 = kq + qd*4;                                                       \
    float4 av = *(const float4*)((arow) + f4*4);                              \
    float4 bv = *(const float4*)((brow) + f4*4);                              \
    int kc = f4*4;                                                            \
    As[(kc+0)*68+lrow]=av.x; As[(kc+1)*68+lrow]=av.y;                         \
    As[(kc+2)*68+lrow]=av.z; As[(kc+3)*68+lrow]=av.w;                         \
    Bs[(kc+0)*68+lrow]=bv.x; Bs[(kc+1)*68+lrow]=bv.y;                         \
    Bs[(kc+2)*68+lrow]=bv.z; Bs[(kc+3)*68+lrow]=bv.w;                         \
  }

// K1: qb/kb/vb[b*512+l][d] = bias[d] + sum_k in[(l*2+b)*512+k]*W[d*512+k]
__global__ void proj_kernel(const float* q, const float* k, const float* v,
                            const float* Wq, const float* bq,
                            const float* Wk, const float* bk,
                            const float* Wv, const float* bv) {
  const float *X, *W, *bias; float* Y;
  int z = blockIdx.z;
  if (z == 0)      { X=q; W=Wq; bias=bq; Y=g_qb; }
  else if (z == 1) { X=k; W=Wk; bias=bk; Y=g_kb; }
  else             { X=v; W=Wv; bias=bv; Y=g_vb; }
  __shared__ __align__(16) float As[64*68];
  __shared__ __align__(16) float Bs[64*68];
  int t = threadIdx.x;
  int m0 = blockIdx.y*64, n0 = blockIdx.x*64;
  int mi = (t & 15)*4, ni = (t >> 4)*4;
  int lrow = t >> 2, kq = t & 3;
  float acc[4][4] = {};
  int r = m0 + lrow;
  const float* xbase = X + ((r & 511)*2 + (r >> 9))*512;
  const float* wbase = W + (n0 + lrow)*512;
  for (int kk0 = 0; kk0 < 512; kk0 += 64) {
    __syncthreads();
    TILE_LOAD(xbase + kk0, wbase + kk0);
    __syncthreads();
    TILE_COMPUTE();
  }
  float4 bias4 = *(const float4*)&bias[n0+ni];
  #pragma unroll
  for (int i = 0; i < 4; i++) {
    float4 o;
    o.x = acc[i][0]+bias4.x; o.y = acc[i][1]+bias4.y;
    o.z = acc[i][2]+bias4.z; o.w = acc[i][3]+bias4.w;
    *(float4*)&Y[(m0+mi+i)*512 + n0+ni] = o;
  }
}

// K2: scores S[b][h][l][m] = dot64(qh, kh) * 0.125  (exact /8)
__global__ void score_kernel() {
  int z = blockIdx.z; int b = z >> 3, h = z & 7;
  int l0 = blockIdx.y*64, m0 = blockIdx.x*64;
  __shared__ __align__(16) float As[64*68];
  __shared__ __align__(16) float Bs[64*68];
  int t = threadIdx.x;
  int mi = (t & 15)*4, ni = (t >> 4)*4;
  int lrow = t >> 2, kq = t & 3;
  float acc[4][4] = {};
  int lq = l0 + lrow, mq = m0 + lrow;
  const float* arow = g_qb + ((b*512 + h*64 + (lq>>3))<<9) + ((lq&7)<<6);
  const float* brow = g_kb + ((b*512 + h*64 + (mq>>3))<<9) + ((mq&7)<<6);
  __syncthreads();
  TILE_LOAD(arow, brow);
  __syncthreads();
  TILE_COMPUTE();
  int base = z*262144;
  #pragma unroll
  for (int i = 0; i < 4; i++) {
    float4 o;
    o.x = acc[i][0]*0.125f; o.y = acc[i][1]*0.125f;
    o.z = acc[i][2]*0.125f; o.w = acc[i][3]*0.125f;
    *(float4*)&g_s[base + (l0+mi+i)*512 + m0+ni] = o;
  }
}

// K3: softmax over heads axis: ascending fp32 max, accurate exp (O1 class),
// ascending fp32 sum, IEEE divide — the reference's arithmetic class.
__global__ void softmax_nv() {
  int g = blockIdx.x*256 + threadIdx.x;   // 524288 columns
  int b = g >> 18;
  int rem = g & 262143;                   // l*512 + m
  int base = b*2097152 + rem;
  float s[8];
  #pragma unroll
  for (int h = 0; h < 8; h++) s[h] = g_s[base + h*262144];
  float M = s[0];
  #pragma unroll
  for (int h = 1; h < 8; h++) M = fmaxf(M, s[h]);
  float e[8]; float den = 0.f;
  #pragma unroll
  for (int h = 0; h < 8; h++) {
    e[h] = __nv_expf(__fsub_rn(s[h], M));
    den = __fadd_rn(den, e[h]);
  }
  #pragma unroll
  for (int h = 0; h < 8; h++) g_attn[base + h*262144] = __fdiv_rn(e[h], den);
}

// K4: per-(b,h,l) row, stable ascending bitonic sort of 512 (value,index) keys,
// then force sub-ulp near-ties (bitdiff <= 1) in the sensitive zone into
// index-ascending order — what the reference's stable sort does when its two
// fp32 attn values land bitwise equal. Keep top 100.
__global__ void topk_kernel() {
  __shared__ unsigned long long keys[512];
  int t = threadIdx.x;
  int bh = blockIdx.y, l = blockIdx.x;
  const float* row = g_attn + (((bh<<9) + l) << 9);
  for (int i = t; i < 512; i += 256)
    keys[i] = (((unsigned long long)__float_as_uint(row[i])) << 32) | (unsigned)i;
  for (int k2 = 2; k2 <= 512; k2 <<= 1)
    for (int jj = k2 >> 1; jj > 0; jj >>= 1) {
      __syncthreads();
      for (int i = t; i < 512; i += 256) {
        int ixj = i ^ jj;
        if (ixj > i) {
          unsigned long long a = keys[i], c = keys[ixj];
          bool sw = ((i & k2) == 0) ? (a > c) : (a < c);
          if (sw) { keys[i] = c; keys[ixj] = a; }
        }
      }
    }
  __syncthreads();
  // Tie-zone fix-up: adjacent values within 1 ulp behave as stable-sort ties.
  if (t == 0) {
    for (int pass = 0; pass < 3; pass++) {
      for (int i = 400; i < 511; i++) {
        unsigned va = (unsigned)(keys[i]   >> 32);
        unsigned vb = (unsigned)(keys[i+1] >> 32);
        unsigned ia = (unsigned)(keys[i]   & 0xffffffffu);
        unsigned ib = (unsigned)(keys[i+1] & 0xffffffffu);
        if (vb - va <= 1u && ia > ib) {
          unsigned long long tmp = keys[i]; keys[i] = keys[i+1]; keys[i+1] = tmp;
        }
      }
    }
  }
  __syncthreads();
  if (t < NUMK)
    g_idx[((bh<<9) + l)*NUMK + t] = (int)(unsigned)(keys[412 + t] & 0xffffffffu);
}

// K5: T[b][lv][cv][j][o] = dot(vb[b][lv][cv*64:+64], Wc[o][j*64:+64])
__global__ void tmat_kernel(const float* Wc) {
  int z = blockIdx.z; int b = z >> 6, cv = (z >> 3) & 7, j = z & 7;
  int lv0 = blockIdx.y*64, o0 = blockIdx.x*64;
  __shared__ __align__(16) float As[64*68];
  __shared__ __align__(16) float Bs[64*68];
  int t = threadIdx.x;
  int mi = (t & 15)*4, ni = (t >> 4)*4;
  int lrow = t >> 2, kq = t & 3;
  float acc[4][4] = {};
  const float* arow = g_vb + ((b*512 + lv0 + lrow)<<9) + (cv<<6);
  const float* brow = Wc + ((o0 + lrow)<<9) + (j<<6);
  __syncthreads();
  TILE_LOAD(arow, brow);
  __syncthreads();
  TILE_COMPUTE();
  #pragma unroll
  for (int i = 0; i < 4; i++) {
    float4 o; o.x = acc[i][0]; o.y = acc[i][1]; o.z = acc[i][2]; o.w = acc[i][3];
    *(float4*)&g_T[((((b*512 + lv0+mi+i)<<3) + cv)*8 + j)*512 + o0+ni] = o;
  }
}

// K6: out[b][l2][n2][o] = bc[o] + sum_j T[b][lv_j][cv_j][j][o]  (gather-sum)
__global__ void final_kernel(const float* bc, float* __restrict__ out) {
  __shared__ int soff[8];
  int t = threadIdx.x;
  int n2 = blockIdx.x, l2 = blockIdx.y, b = blockIdx.z;
  if (t < 8) {
    int j = t;
    int h = l2 >> 6;
    int u = (l2 & 63)*800 + n2*8 + j;
    int lq = u / 100, n = u % 100;
    int m = g_idx[(((b<<3) + h)*512 + lq)*NUMK + n];
    int lv = (h<<6) + (m >> 3), cv = m & 7;
    soff[j] = ((((b*512 + lv)<<3) + cv)*8 + j) << 9;
  }
  __syncthreads();
  int o = t << 2;
  float4 acc = *(const float4*)&bc[o];
  #pragma unroll
  for (int j = 0; j < 8; j++) {
    float4 v = *(const float4*)&g_T[soff[j] + o];
    acc.x += v.x; acc.y += v.y; acc.z += v.z; acc.w += v.w;
  }
  *(float4*)&out[((((b<<9) + l2)*NUMK + n2) << 9) + o] = acc;
}

extern "C" void kernel_launch(void* const* d_in, const int* in_sizes, int n_in,
                              void* d_out, int out_size) {
  const float* q  = (const float*)d_in[0];
  const float* k  = (const float*)d_in[1];
  const float* v  = (const float*)d_in[2];
  const float* Wq = (const float*)d_in[3];
  const float* bq = (const float*)d_in[4];
  const float* Wk = (const float*)d_in[5];
  const float* bk = (const float*)d_in[6];
  const float* Wv = (const float*)d_in[7];
  const float* bv = (const float*)d_in[8];
  const float* Wc = (const float*)d_in[9];
  const float* bc = (const float*)d_in[10];

  proj_kernel  <<<dim3(8, 16, 3),  256>>>(q, k, v, Wq, bq, Wk, bk, Wv, bv);
  score_kernel <<<dim3(8, 8, 16),  256>>>();
  softmax_nv   <<<2048,            256>>>();
  topk_kernel  <<<dim3(512, 16),   256>>>();
  tmat_kernel  <<<dim3(8, 8, 128), 256>>>(Wc);
  final_kernel <<<dim3(100, 512, 2), 128>>>(bc, (float*)d_out);
}

// round 16
// speedup vs baseline: 1.1292x; 1.1292x over previous
#include <cuda_runtime.h>
#include <cuda_fp16.h>
#include <math.h>

#define LL 512
#define BB 2
#define DD 512
#define HH 8
#define DTT 64
#define NUMK 100

// libdevice accurate expf (O1 class — matches reference softmax arithmetic class)
extern "C" __device__ float __nv_expf(float);

// ---- scratch (device globals, allowed) ----
__device__ float  g_qb[BB*LL*DD];          // [b][l][d]
__device__ float  g_kb[BB*LL*DD];
__device__ float  g_vb[BB*LL*DD];
__device__ float  g_s[BB*HH*LL*LL];        // raw scores /8: [b][h][l][m]
__device__ float  g_attn[BB*HH*LL*LL];     // softmax
__device__ int    g_idx[BB*HH*LL*NUMK];    // top-100 ascending indices
__device__ __half g_T[BB*LL*8*8*DD];       // [b][lv][cv][j][o]  (64 MB, fp16)

// 16 FMA micro-tile over a 64-deep K chunk, smem pitch 68 floats.
#define TILE_COMPUTE()                                                        \
  _Pragma("unroll")                                                           \
  for (int kc = 0; kc < 64; kc++) {                                           \
    float4 a  = *(const float4*)(As + kc*68 + mi);                            \
    float4 b4 = *(const float4*)(Bs + kc*68 + ni);                            \
    acc[0][0] = fmaf(a.x,b4.x,acc[0][0]); acc[0][1] = fmaf(a.x,b4.y,acc[0][1]);\
    acc[0][2] = fmaf(a.x,b4.z,acc[0][2]); acc[0][3] = fmaf(a.x,b4.w,acc[0][3]);\
    acc[1][0] = fmaf(a.y,b4.x,acc[1][0]); acc[1][1] = fmaf(a.y,b4.y,acc[1][1]);\
    acc[1][2] = fmaf(a.y,b4.z,acc[1][2]); acc[1][3] = fmaf(a.y,b4.w,acc[1][3]);\
    acc[2][0] = fmaf(a.z,b4.x,acc[2][0]); acc[2][1] = fmaf(a.z,b4.y,acc[2][1]);\
    acc[2][2] = fmaf(a.z,b4.z,acc[2][2]); acc[2][3] = fmaf(a.z,b4.w,acc[2][3]);\
    acc[3][0] = fmaf(a.w,b4.x,acc[3][0]); acc[3][1] = fmaf(a.w,b4.y,acc[3][1]);\
    acc[3][2] = fmaf(a.w,b4.z,acc[3][2]); acc[3][3] = fmaf(a.w,b4.w,acc[3][3]);\
  }

#define TILE_LOAD(arow, brow)                                                 \
  _Pragma("unroll")                                                           \
  for (int qd = 0; qd < 4; qd++) {                                            \
    int f4 = kq + qd*4;                                                       \
    float4 av = *(const float4*)((arow) + f4*4);                              \
    float4 bv = *(const float4*)((brow) + f4*4);                              \
    int kc = f4*4;                                                            \
    As[(kc+0)*68+lrow]=av.x; As[(kc+1)*68+lrow]=av.y;                         \
    As[(kc+2)*68+lrow]=av.z; As[(kc+3)*68+lrow]=av.w;                         \
    Bs[(kc+0)*68+lrow]=bv.x; Bs[(kc+1)*68+lrow]=bv.y;                         \
    Bs[(kc+2)*68+lrow]=bv.z; Bs[(kc+3)*68+lrow]=bv.w;                         \
  }

// K1: qb/kb/vb[b*512+l][d] = bias[d] + sum_k in[(l*2+b)*512+k]*W[d*512+k]
__global__ void proj_kernel(const float* q, const float* k, const float* v,
                            const float* Wq, const float* bq,
                            const float* Wk, const float* bk,
                            const float* Wv, const float* bv) {
  const float *X, *W, *bias; float* Y;
  int z = blockIdx.z;
  if (z == 0)      { X=q; W=Wq; bias=bq; Y=g_qb; }
  else if (z == 1) { X=k; W=Wk; bias=bk; Y=g_kb; }
  else             { X=v; W=Wv; bias=bv; Y=g_vb; }
  __shared__ __align__(16) float As[64*68];
  __shared__ __align__(16) float Bs[64*68];
  int t = threadIdx.x;
  int m0 = blockIdx.y*64, n0 = blockIdx.x*64;
  int mi = (t & 15)*4, ni = (t >> 4)*4;
  int lrow = t >> 2, kq = t & 3;
  float acc[4][4] = {};
  int r = m0 + lrow;
  const float* xbase = X + ((r & 511)*2 + (r >> 9))*512;
  const float* wbase = W + (n0 + lrow)*512;
  for (int kk0 = 0; kk0 < 512; kk0 += 64) {
    __syncthreads();
    TILE_LOAD(xbase + kk0, wbase + kk0);
    __syncthreads();
    TILE_COMPUTE();
  }
  float4 bias4 = *(const float4*)&bias[n0+ni];
  #pragma unroll
  for (int i = 0; i < 4; i++) {
    float4 o;
    o.x = acc[i][0]+bias4.x; o.y = acc[i][1]+bias4.y;
    o.z = acc[i][2]+bias4.z; o.w = acc[i][3]+bias4.w;
    *(float4*)&Y[(m0+mi+i)*512 + n0+ni] = o;
  }
}

// K2: scores S[b][h][l][m] = dot64(qh, kh) * 0.125  (exact /8)
__global__ void score_kernel() {
  int z = blockIdx.z; int b = z >> 3, h = z & 7;
  int l0 = blockIdx.y*64, m0 = blockIdx.x*64;
  __shared__ __align__(16) float As[64*68];
  __shared__ __align__(16) float Bs[64*68];
  int t = threadIdx.x;
  int mi = (t & 15)*4, ni = (t >> 4)*4;
  int lrow = t >> 2, kq = t & 3;
  float acc[4][4] = {};
  int lq = l0 + lrow, mq = m0 + lrow;
  const float* arow = g_qb + ((b*512 + h*64 + (lq>>3))<<9) + ((lq&7)<<6);
  const float* brow = g_kb + ((b*512 + h*64 + (mq>>3))<<9) + ((mq&7)<<6);
  __syncthreads();
  TILE_LOAD(arow, brow);
  __syncthreads();
  TILE_COMPUTE();
  int base = z*262144;
  #pragma unroll
  for (int i = 0; i < 4; i++) {
    float4 o;
    o.x = acc[i][0]*0.125f; o.y = acc[i][1]*0.125f;
    o.z = acc[i][2]*0.125f; o.w = acc[i][3]*0.125f;
    *(float4*)&g_s[base + (l0+mi+i)*512 + m0+ni] = o;
  }
}

// K3: softmax over heads axis: ascending fp32 max, accurate exp, ascending sum, IEEE div
__global__ void softmax_nv() {
  int g = blockIdx.x*256 + threadIdx.x;   // 524288 columns
  int b = g >> 18;
  int rem = g & 262143;                   // l*512 + m
  int base = b*2097152 + rem;
  float s[8];
  #pragma unroll
  for (int h = 0; h < 8; h++) s[h] = g_s[base + h*262144];
  float M = s[0];
  #pragma unroll
  for (int h = 1; h < 8; h++) M = fmaxf(M, s[h]);
  float e[8]; float den = 0.f;
  #pragma unroll
  for (int h = 0; h < 8; h++) {
    e[h] = __nv_expf(__fsub_rn(s[h], M));
    den = __fadd_rn(den, e[h]);
  }
  #pragma unroll
  for (int h = 0; h < 8; h++) g_attn[base + h*262144] = __fdiv_rn(e[h], den);
}

// K4: stable ascending bitonic sort (identical pass order; syncwarp for provably
// intra-warp passes), tie-zone stable fix-up (skipped when no candidates).
__global__ void topk_kernel() {
  __shared__ unsigned long long keys[512];
  __shared__ int tieflag;
  int t = threadIdx.x;
  int bh = blockIdx.y, l = blockIdx.x;
  const float* row = g_attn + (((bh<<9) + l) << 9);
  for (int i = t; i < 512; i += 256)
    keys[i] = (((unsigned long long)__float_as_uint(row[i])) << 32) | (unsigned)i;
  if (t == 0) tieflag = 0;
  bool prev_cross = false;
  for (int k2 = 2; k2 <= 512; k2 <<= 1)
    for (int jj = k2 >> 1; jj > 0; jj >>= 1) {
      bool cross = (jj >= 32);
      if (cross || prev_cross) __syncthreads(); else __syncwarp();
      #pragma unroll
      for (int rep = 0; rep < 2; rep++) {
        int i = t + rep*256;
        int ixj = i ^ jj;
        if (ixj > i) {
          unsigned long long a = keys[i], c = keys[ixj];
          bool sw = ((i & k2) == 0) ? (a > c) : (a < c);
          if (sw) { keys[i] = c; keys[ixj] = a; }
        }
      }
      prev_cross = cross;
    }
  __syncthreads();
  // Parallel tie-candidate detection over the sensitive zone.
  if (t < 111) {
    int i = 400 + t;
    unsigned va = (unsigned)(keys[i]   >> 32);
    unsigned vb = (unsigned)(keys[i+1] >> 32);
    unsigned ia = (unsigned)(keys[i]   & 0xffffffffu);
    unsigned ib = (unsigned)(keys[i+1] & 0xffffffffu);
    if (vb - va <= 1u && ia > ib) tieflag = 1;
  }
  __syncthreads();
  if (tieflag && t == 0) {
    for (int pass = 0; pass < 3; pass++) {
      for (int i = 400; i < 511; i++) {
        unsigned va = (unsigned)(keys[i]   >> 32);
        unsigned vb = (unsigned)(keys[i+1] >> 32);
        unsigned ia = (unsigned)(keys[i]   & 0xffffffffu);
        unsigned ib = (unsigned)(keys[i+1] & 0xffffffffu);
        if (vb - va <= 1u && ia > ib) {
          unsigned long long tmp = keys[i]; keys[i] = keys[i+1]; keys[i+1] = tmp;
        }
      }
    }
  }
  __syncthreads();
  if (t < NUMK)
    g_idx[((bh<<9) + l)*NUMK + t] = (int)(unsigned)(keys[412 + t] & 0xffffffffu);
}

// K5: T[b][lv][cv][j][o] = dot(vb[b][lv][cv*64:+64], Wc[o][j*64:+64]) -> fp16
__global__ void tmat_kernel(const float* Wc) {
  int z = blockIdx.z; int b = z >> 6, cv = (z >> 3) & 7, j = z & 7;
  int lv0 = blockIdx.y*64, o0 = blockIdx.x*64;
  __shared__ __align__(16) float As[64*68];
  __shared__ __align__(16) float Bs[64*68];
  int t = threadIdx.x;
  int mi = (t & 15)*4, ni = (t >> 4)*4;
  int lrow = t >> 2, kq = t & 3;
  float acc[4][4] = {};
  const float* arow = g_vb + ((b*512 + lv0 + lrow)<<9) + (cv<<6);
  const float* brow = Wc + ((o0 + lrow)<<9) + (j<<6);
  __syncthreads();
  TILE_LOAD(arow, brow);
  __syncthreads();
  TILE_COMPUTE();
  #pragma unroll
  for (int i = 0; i < 4; i++) {
    union { uint2 u; __half2 h[2]; } pk;
    pk.h[0] = __floats2half2_rn(acc[i][0], acc[i][1]);
    pk.h[1] = __floats2half2_rn(acc[i][2], acc[i][3]);
    *(uint2*)&g_T[((((b*512 + lv0+mi+i)<<3) + cv)*8 + j)*512 + o0+ni] = pk.u;
  }
}

// K6: out[b][l2][n2][o] = bc[o] + sum_j T[b][lv_j][cv_j][j][o]  (fp16 gather-sum)
__global__ void final_kernel(const float* bc, float* __restrict__ out) {
  __shared__ int soff[8];
  int t = threadIdx.x;
  int n2 = blockIdx.x, l2 = blockIdx.y, b = blockIdx.z;
  if (t < 8) {
    int j = t;
    int h = l2 >> 6;
    int u = (l2 & 63)*800 + n2*8 + j;
    int lq = u / 100, n = u % 100;
    int m = g_idx[(((b<<3) + h)*512 + lq)*NUMK + n];
    int lv = (h<<6) + (m >> 3), cv = m & 7;
    soff[j] = ((((b*512 + lv)<<3) + cv)*8 + j) << 9;
  }
  __syncthreads();
  int o = t << 2;
  float4 acc = *(const float4*)&bc[o];
  #pragma unroll
  for (int j = 0; j < 8; j++) {
    union { uint2 u; __half2 h[2]; } pk;
    pk.u = *(const uint2*)&g_T[soff[j] + o];
    float2 f0 = __half22float2(pk.h[0]);
    float2 f1 = __half22float2(pk.h[1]);
    acc.x += f0.x; acc.y += f0.y; acc.z += f1.x; acc.w += f1.y;
  }
  *(float4*)&out[((((b<<9) + l2)*NUMK + n2) << 9) + o] = acc;
}

extern "C" void kernel_launch(void* const* d_in, const int* in_sizes, int n_in,
                              void* d_out, int out_size) {
  const float* q  = (const float*)d_in[0];
  const float* k  = (const float*)d_in[1];
  const float* v  = (const float*)d_in[2];
  const float* Wq = (const float*)d_in[3];
  const float* bq = (const float*)d_in[4];
  const float* Wk = (const float*)d_in[5];
  const float* bk = (const float*)d_in[6];
  const float* Wv = (const float*)d_in[7];
  const float* bv = (const float*)d_in[8];
  const float* Wc = (const float*)d_in[9];
  const float* bc = (const float*)d_in[10];

  proj_kernel  <<<dim3(8, 16, 3),  256>>>(q, k, v, Wq, bq, Wk, bk, Wv, bv);
  score_kernel <<<dim3(8, 8, 16),  256>>>();
  softmax_nv   <<<2048,            256>>>();
  topk_kernel  <<<dim3(512, 16),   256>>>();
  tmat_kernel  <<<dim3(8, 8, 128), 256>>>(Wc);
  final_kernel <<<dim3(100, 512, 2), 128>>>(bc, (float*)d_out);
}